// round 11
// baseline (speedup 1.0000x reference)
#include <cuda_runtime.h>
#include <cuda_fp16.h>
#include <mma.h>
#include <math.h>

using namespace nvcuda;

#define N_NODES 50000
#define E_EDGES 800000
#define ETOT    (E_EDGES + N_NODES)   // 850000
#define F_IN    128
#define HID     64
#define HEADS   4
#define C1      (HEADS * HID)         // 256
#define SLOPE   0.2f
#define EPS_SM  1e-16f

#define SCAN_T  1024
#define SCAN_CH 52                     // 52*1024 = 53248 >= N_NODES, /4
#define N_PAD   (SCAN_T * SCAN_CH)

// wmma gemm1 tiling
#define G1_BM    64
#define G1_ALD   136
#define G1_WLD   264
#define G1_SLD   264
#define G1_SMEM  ((G1_BM * G1_ALD + 128 * G1_WLD) * 2 > G1_BM * G1_SLD * 4 ? \
                  (G1_BM * G1_ALD + 128 * G1_WLD) * 2 : G1_BM * G1_SLD * 4)

// wmma gemm2 tiling (64 rows x 64 cols x K=256, 4 warps)
#define G2_BM    64
#define G2_ALD   264
#define G2_WLD   72
#define G2_SLD   72
#define G2_SMEM  ((G2_BM * G2_ALD + 256 * G2_WLD) * 2)

// ------------------------- device scratch (no allocs allowed) ---------------
__device__ __half g_h1h[(size_t)N_NODES * C1];    // x @ W1 (fp16 storage)
__device__ float  g_x2 [(size_t)N_NODES * C1];    // layer1 output after LN/ELU
__device__ __half g_h2h[(size_t)N_NODES * HID];   // x2 @ W2 (fp16 storage)
__device__ __half g_w1h[F_IN * C1];
__device__ __half g_w2h[C1 * HID];
__device__ float g_s1  [N_NODES * HEADS];
__device__ float g_d1  [N_NODES * HEADS];
__device__ float g_s2  [N_NODES];
__device__ float g_d2  [N_NODES];
// CSR by destination (rebuilt every launch; deterministic work)
__device__ __align__(16) int g_cnt   [N_PAD];
__device__ __align__(16) int g_rowptr[N_PAD + 4];
__device__ __align__(16) int g_wofs  [N_PAD + 4];
__device__ int2 g_epack[ETOT];                    // {src, eid} per CSR slot
// fallback alpha scratch in case d_out layout differs from expectation
__device__ float g_a1_fb[(size_t)ETOT * HEADS];
__device__ float g_a2_fb[(size_t)ETOT];

// ------------------------- helpers ------------------------------------------
__device__ __forceinline__ float lrelu(float v) { return v > 0.f ? v : SLOPE * v; }
__device__ __forceinline__ float eluf(float v)  { return v > 0.f ? v : expm1f(v); }

__device__ __forceinline__ float wredsum(float v) {
#pragma unroll
    for (int o = 16; o > 0; o >>= 1) v += __shfl_xor_sync(0xffffffffu, v, o);
    return v;
}

__device__ __forceinline__ uint2 pack_half4(float4 v) {
    __half2 h0 = __floats2half2_rn(v.x, v.y);
    __half2 h1 = __floats2half2_rn(v.z, v.w);
    return make_uint2(*reinterpret_cast<unsigned*>(&h0),
                      *reinterpret_cast<unsigned*>(&h1));
}

// ------------------------- CSR build -----------------------------------------
__global__ void zero_cnt_kernel() {
    int i = blockIdx.x * blockDim.x + threadIdx.x;
    if (i < N_PAD / 4) *reinterpret_cast<int4*>(&g_cnt[i * 4]) = make_int4(0, 0, 0, 0);
}

__global__ void hist_kernel(const int* __restrict__ ei) {
    int i0 = (blockIdx.x * blockDim.x + threadIdx.x) * 8;
    if (i0 >= ETOT) return;
    if (i0 + 8 <= E_EDGES) {
        int4 d0 = *reinterpret_cast<const int4*>(&ei[E_EDGES + i0]);
        int4 d1 = *reinterpret_cast<const int4*>(&ei[E_EDGES + i0 + 4]);
        atomicAdd(&g_cnt[d0.x], 1); atomicAdd(&g_cnt[d0.y], 1);
        atomicAdd(&g_cnt[d0.z], 1); atomicAdd(&g_cnt[d0.w], 1);
        atomicAdd(&g_cnt[d1.x], 1); atomicAdd(&g_cnt[d1.y], 1);
        atomicAdd(&g_cnt[d1.z], 1); atomicAdd(&g_cnt[d1.w], 1);
    } else {
#pragma unroll
        for (int t = 0; t < 8; t++) {
            int e = i0 + t;
            if (e < ETOT) {
                int dst = (e < E_EDGES) ? ei[E_EDGES + e] : e - E_EDGES;
                atomicAdd(&g_cnt[dst], 1);
            }
        }
    }
}

__global__ __launch_bounds__(SCAN_T) void scan_kernel() {
    __shared__ int sums[SCAN_T];
    int t = threadIdx.x;
    int lo = t * SCAN_CH;
    const int4* cp = reinterpret_cast<const int4*>(&g_cnt[lo]);
    int local = 0;
#pragma unroll
    for (int i = 0; i < SCAN_CH / 4; i++) {
        int4 c = cp[i];
        local += c.x + c.y + c.z + c.w;
    }
    sums[t] = local;
    __syncthreads();
    for (int off = 1; off < SCAN_T; off <<= 1) {
        int v = (t >= off) ? sums[t - off] : 0;
        __syncthreads();
        sums[t] += v;
        __syncthreads();
    }
    int run = sums[t] - local;
    int4* rp = reinterpret_cast<int4*>(&g_rowptr[lo]);
    int4* wp = reinterpret_cast<int4*>(&g_wofs[lo]);
#pragma unroll
    for (int i = 0; i < SCAN_CH / 4; i++) {
        int4 c = cp[i];
        int4 o;
        o.x = run; run += c.x;
        o.y = run; run += c.y;
        o.z = run; run += c.z;
        o.w = run; run += c.w;
        rp[i] = o; wp[i] = o;
    }
}

__global__ void scatter_kernel(const int* __restrict__ ei) {
    int i0 = (blockIdx.x * blockDim.x + threadIdx.x) * 8;
    if (i0 >= ETOT) return;
    if (i0 + 8 <= E_EDGES) {
        int4 s0 = *reinterpret_cast<const int4*>(&ei[i0]);
        int4 s1 = *reinterpret_cast<const int4*>(&ei[i0 + 4]);
        int4 d0 = *reinterpret_cast<const int4*>(&ei[E_EDGES + i0]);
        int4 d1 = *reinterpret_cast<const int4*>(&ei[E_EDGES + i0 + 4]);
        int sl;
        sl = atomicAdd(&g_wofs[d0.x], 1); g_epack[sl] = make_int2(s0.x, i0);
        sl = atomicAdd(&g_wofs[d0.y], 1); g_epack[sl] = make_int2(s0.y, i0 + 1);
        sl = atomicAdd(&g_wofs[d0.z], 1); g_epack[sl] = make_int2(s0.z, i0 + 2);
        sl = atomicAdd(&g_wofs[d0.w], 1); g_epack[sl] = make_int2(s0.w, i0 + 3);
        sl = atomicAdd(&g_wofs[d1.x], 1); g_epack[sl] = make_int2(s1.x, i0 + 4);
        sl = atomicAdd(&g_wofs[d1.y], 1); g_epack[sl] = make_int2(s1.y, i0 + 5);
        sl = atomicAdd(&g_wofs[d1.z], 1); g_epack[sl] = make_int2(s1.z, i0 + 6);
        sl = atomicAdd(&g_wofs[d1.w], 1); g_epack[sl] = make_int2(s1.w, i0 + 7);
    } else {
#pragma unroll
        for (int t = 0; t < 8; t++) {
            int e = i0 + t;
            if (e < ETOT) {
                int src, dst;
                if (e < E_EDGES) { src = ei[e]; dst = ei[E_EDGES + e]; }
                else             { src = dst = e - E_EDGES; }
                int slot = atomicAdd(&g_wofs[dst], 1);
                g_epack[slot] = make_int2(src, e);
            }
        }
    }
}

// ------------------------- W1+W2 fp32 -> fp16 (once per launch) --------------
__global__ void conv_w_kernel(const float* __restrict__ W1,
                              const float* __restrict__ W2) {
    int i4 = (blockIdx.x * blockDim.x + threadIdx.x) * 4;
    if (i4 < F_IN * C1) {
        float4 v = *reinterpret_cast<const float4*>(&W1[i4]);
        *reinterpret_cast<uint2*>(&g_w1h[i4]) = pack_half4(v);
    } else if (i4 < F_IN * C1 + C1 * HID) {
        int j4 = i4 - F_IN * C1;
        float4 v = *reinterpret_cast<const float4*>(&W2[j4]);
        *reinterpret_cast<uint2*>(&g_w2h[j4]) = pack_half4(v);
    }
}

// ---- layer-1 GEMM on tensor cores (HMMA) + fused logits ---------------------
__global__ __launch_bounds__(256)
void gemm1_wmma_kernel(const float* __restrict__ X,
                       const float* __restrict__ asrc, const float* __restrict__ adst,
                       __half* __restrict__ Yh,
                       float* __restrict__ S, float* __restrict__ D, int nrows) {
    extern __shared__ char smraw[];
    __half* Ah  = reinterpret_cast<__half*>(smraw);
    __half* Wh  = reinterpret_cast<__half*>(smraw) + G1_BM * G1_ALD;
    float*  stg = reinterpret_cast<float*>(smraw);

    int tid = threadIdx.x;
    int rowbase = blockIdx.x * G1_BM;

    for (int i = tid * 4; i < G1_BM * F_IN; i += 256 * 4) {
        int r = i >> 7, c = i & 127;
        int gr = rowbase + r;
        float4 v = (gr < nrows) ? *reinterpret_cast<const float4*>(&X[(size_t)gr * F_IN + c])
                                : make_float4(0.f, 0.f, 0.f, 0.f);
        *reinterpret_cast<uint2*>(&Ah[r * G1_ALD + c]) = pack_half4(v);
    }
    for (int i = tid * 8; i < F_IN * C1; i += 256 * 8) {
        int k = i >> 8, c = i & 255;
        uint4 v = *reinterpret_cast<const uint4*>(&g_w1h[i]);
        *reinterpret_cast<uint4*>(&Wh[k * G1_WLD + c]) = v;
    }
    __syncthreads();

    int w = tid >> 5;
    int r0 = (w & 3) * 16;
    int cb = (w >> 2) * 128;

    wmma::fragment<wmma::accumulator, 16, 16, 16, float> acc[8];
#pragma unroll
    for (int f = 0; f < 8; f++) wmma::fill_fragment(acc[f], 0.f);

#pragma unroll
    for (int kk = 0; kk < F_IN; kk += 16) {
        wmma::fragment<wmma::matrix_a, 16, 16, 16, __half, wmma::row_major> af;
        wmma::load_matrix_sync(af, Ah + r0 * G1_ALD + kk, G1_ALD);
#pragma unroll
        for (int f = 0; f < 8; f++) {
            wmma::fragment<wmma::matrix_b, 16, 16, 16, __half, wmma::row_major> bf;
            wmma::load_matrix_sync(bf, Wh + kk * G1_WLD + cb + f * 16, G1_WLD);
            wmma::mma_sync(acc[f], af, bf, acc[f]);
        }
    }
    __syncthreads();
#pragma unroll
    for (int f = 0; f < 8; f++)
        wmma::store_matrix_sync(stg + r0 * G1_SLD + cb + f * 16, acc[f],
                                G1_SLD, wmma::mem_row_major);
    __syncthreads();

    int r = tid >> 2, q = tid & 3;
    int gr = rowbase + r;
    if (gr < nrows) {
        const float* as = asrc + q * 64;
        const float* ad = adst + q * 64;
        const float* row = stg + r * G1_SLD + q * 64;
        __half* yp = Yh + (size_t)gr * C1 + q * 64;
        float s = 0.f, dd = 0.f;
#pragma unroll
        for (int i = 0; i < 64; i += 4) {
            float4 v = *reinterpret_cast<const float4*>(&row[i]);
            float4 a = *reinterpret_cast<const float4*>(&as[i]);
            float4 b = *reinterpret_cast<const float4*>(&ad[i]);
            s  += v.x * a.x + v.y * a.y + v.z * a.z + v.w * a.w;
            dd += v.x * b.x + v.y * b.y + v.z * b.z + v.w * b.w;
            *reinterpret_cast<uint2*>(&yp[i]) = pack_half4(v);
        }
        S[gr * 4 + q] = s;
        D[gr * 4 + q] = dd;
    }
}

// ---- layer-2 GEMM on tensor cores (HMMA) + fused logits ---------------------
__global__ __launch_bounds__(128)
void gemm2_wmma_kernel(const float* __restrict__ X,
                       const float* __restrict__ asrc, const float* __restrict__ adst,
                       __half* __restrict__ Yh,
                       float* __restrict__ S, float* __restrict__ D, int nrows) {
    extern __shared__ char smraw[];
    __half* Ah  = reinterpret_cast<__half*>(smraw);
    __half* Wh  = reinterpret_cast<__half*>(smraw) + G2_BM * G2_ALD;
    float*  stg = reinterpret_cast<float*>(smraw);

    int tid = threadIdx.x;
    int rowbase = blockIdx.x * G2_BM;

    for (int i = tid * 4; i < G2_BM * C1; i += 128 * 4) {
        int r = i >> 8, c = i & 255;
        int gr = rowbase + r;
        float4 v = (gr < nrows) ? *reinterpret_cast<const float4*>(&X[(size_t)gr * C1 + c])
                                : make_float4(0.f, 0.f, 0.f, 0.f);
        *reinterpret_cast<uint2*>(&Ah[r * G2_ALD + c]) = pack_half4(v);
    }
    for (int i = tid * 8; i < C1 * HID; i += 128 * 8) {
        int k = i >> 6, c = i & 63;
        uint4 v = *reinterpret_cast<const uint4*>(&g_w2h[i]);
        *reinterpret_cast<uint4*>(&Wh[k * G2_WLD + c]) = v;
    }
    __syncthreads();

    int w = tid >> 5;
    int r0 = w * 16;

    wmma::fragment<wmma::accumulator, 16, 16, 16, float> acc[4];
#pragma unroll
    for (int f = 0; f < 4; f++) wmma::fill_fragment(acc[f], 0.f);

#pragma unroll
    for (int kk = 0; kk < C1; kk += 16) {
        wmma::fragment<wmma::matrix_a, 16, 16, 16, __half, wmma::row_major> af;
        wmma::load_matrix_sync(af, Ah + r0 * G2_ALD + kk, G2_ALD);
#pragma unroll
        for (int f = 0; f < 4; f++) {
            wmma::fragment<wmma::matrix_b, 16, 16, 16, __half, wmma::row_major> bf;
            wmma::load_matrix_sync(bf, Wh + kk * G2_WLD + f * 16, G2_WLD);
            wmma::mma_sync(acc[f], af, bf, acc[f]);
        }
    }
    __syncthreads();
#pragma unroll
    for (int f = 0; f < 4; f++)
        wmma::store_matrix_sync(stg + r0 * G2_SLD + f * 16, acc[f],
                                G2_SLD, wmma::mem_row_major);
    __syncthreads();

    int r = tid >> 1, half = tid & 1;
    int c0 = half * 32;
    int gr = rowbase + r;
    float s = 0.f, dd = 0.f;
    if (gr < nrows) {
        const float* row = stg + r * G2_SLD + c0;
        __half* yp = Yh + (size_t)gr * HID + c0;
#pragma unroll
        for (int i = 0; i < 32; i += 4) {
            float4 v = *reinterpret_cast<const float4*>(&row[i]);
            float4 a = *reinterpret_cast<const float4*>(&asrc[c0 + i]);
            float4 b = *reinterpret_cast<const float4*>(&adst[c0 + i]);
            s  += v.x * a.x + v.y * a.y + v.z * a.z + v.w * a.w;
            dd += v.x * b.x + v.y * b.y + v.z * b.z + v.w * b.w;
            *reinterpret_cast<uint2*>(&yp[i]) = pack_half4(v);
        }
    }
    s  += __shfl_xor_sync(0xffffffffu, s, 1);
    dd += __shfl_xor_sync(0xffffffffu, dd, 1);
    if (gr < nrows && half == 0) { S[gr] = s; D[gr] = dd; }
}

// ------------------------- layer 1: single-pass gather + LN + ELU ------------
// 4-edge unroll: 8+ outstanding LDGs per lane against L2 latency
__global__ __launch_bounds__(256)
void agg1_kernel(float* __restrict__ a1, const float* __restrict__ b1,
                 const float* __restrict__ gam, const float* __restrict__ bet) {
    int n    = (blockIdx.x * blockDim.x + threadIdx.x) >> 5;
    int lane = threadIdx.x & 31;
    if (n >= N_NODES) return;
    int base = g_rowptr[n], end = g_rowptr[n + 1];
    float4 d = *reinterpret_cast<const float4*>(&g_d1[n * 4]);

    int h  = lane >> 3;
    int c0 = lane * 8;
    float acc[8];
#pragma unroll
    for (int i = 0; i < 8; i++) acc[i] = 0.f;
    float4 den = make_float4(0.f, 0.f, 0.f, 0.f);

    int j = base;
    for (; j + 3 < end; j += 4) {
        int2 p0 = g_epack[j],     p1 = g_epack[j + 1];
        int2 p2 = g_epack[j + 2], p3 = g_epack[j + 3];
        float4 s0 = *reinterpret_cast<const float4*>(&g_s1[p0.x * 4]);
        float4 s1 = *reinterpret_cast<const float4*>(&g_s1[p1.x * 4]);
        float4 s2 = *reinterpret_cast<const float4*>(&g_s1[p2.x * 4]);
        float4 s3 = *reinterpret_cast<const float4*>(&g_s1[p3.x * 4]);
        uint4 hv0 = *reinterpret_cast<const uint4*>(&g_h1h[(size_t)p0.x * C1 + c0]);
        uint4 hv1 = *reinterpret_cast<const uint4*>(&g_h1h[(size_t)p1.x * C1 + c0]);
        uint4 hv2 = *reinterpret_cast<const uint4*>(&g_h1h[(size_t)p2.x * C1 + c0]);
        uint4 hv3 = *reinterpret_cast<const uint4*>(&g_h1h[(size_t)p3.x * C1 + c0]);
        float4 e0, e1, e2, e3;
        e0.x = __expf(lrelu(s0.x + d.x)); e0.y = __expf(lrelu(s0.y + d.y));
        e0.z = __expf(lrelu(s0.z + d.z)); e0.w = __expf(lrelu(s0.w + d.w));
        e1.x = __expf(lrelu(s1.x + d.x)); e1.y = __expf(lrelu(s1.y + d.y));
        e1.z = __expf(lrelu(s1.z + d.z)); e1.w = __expf(lrelu(s1.w + d.w));
        e2.x = __expf(lrelu(s2.x + d.x)); e2.y = __expf(lrelu(s2.y + d.y));
        e2.z = __expf(lrelu(s2.z + d.z)); e2.w = __expf(lrelu(s2.w + d.w));
        e3.x = __expf(lrelu(s3.x + d.x)); e3.y = __expf(lrelu(s3.y + d.y));
        e3.z = __expf(lrelu(s3.z + d.z)); e3.w = __expf(lrelu(s3.w + d.w));
        den.x += (e0.x + e1.x) + (e2.x + e3.x);
        den.y += (e0.y + e1.y) + (e2.y + e3.y);
        den.z += (e0.z + e1.z) + (e2.z + e3.z);
        den.w += (e0.w + e1.w) + (e2.w + e3.w);
        float a0 = (h == 0) ? e0.x : (h == 1) ? e0.y : (h == 2) ? e0.z : e0.w;
        float a1w = (h == 0) ? e1.x : (h == 1) ? e1.y : (h == 2) ? e1.z : e1.w;
        float a2 = (h == 0) ? e2.x : (h == 1) ? e2.y : (h == 2) ? e2.z : e2.w;
        float a3 = (h == 0) ? e3.x : (h == 1) ? e3.y : (h == 2) ? e3.z : e3.w;
        float2 f00 = __half22float2(*reinterpret_cast<__half2*>(&hv0.x));
        float2 f01 = __half22float2(*reinterpret_cast<__half2*>(&hv0.y));
        float2 f02 = __half22float2(*reinterpret_cast<__half2*>(&hv0.z));
        float2 f03 = __half22float2(*reinterpret_cast<__half2*>(&hv0.w));
        float2 f10 = __half22float2(*reinterpret_cast<__half2*>(&hv1.x));
        float2 f11 = __half22float2(*reinterpret_cast<__half2*>(&hv1.y));
        float2 f12 = __half22float2(*reinterpret_cast<__half2*>(&hv1.z));
        float2 f13 = __half22float2(*reinterpret_cast<__half2*>(&hv1.w));
        float2 f20 = __half22float2(*reinterpret_cast<__half2*>(&hv2.x));
        float2 f21 = __half22float2(*reinterpret_cast<__half2*>(&hv2.y));
        float2 f22 = __half22float2(*reinterpret_cast<__half2*>(&hv2.z));
        float2 f23 = __half22float2(*reinterpret_cast<__half2*>(&hv2.w));
        float2 f30 = __half22float2(*reinterpret_cast<__half2*>(&hv3.x));
        float2 f31 = __half22float2(*reinterpret_cast<__half2*>(&hv3.y));
        float2 f32 = __half22float2(*reinterpret_cast<__half2*>(&hv3.z));
        float2 f33 = __half22float2(*reinterpret_cast<__half2*>(&hv3.w));
        acc[0] += (f00.x * a0 + f10.x * a1w) + (f20.x * a2 + f30.x * a3);
        acc[1] += (f00.y * a0 + f10.y * a1w) + (f20.y * a2 + f30.y * a3);
        acc[2] += (f01.x * a0 + f11.x * a1w) + (f21.x * a2 + f31.x * a3);
        acc[3] += (f01.y * a0 + f11.y * a1w) + (f21.y * a2 + f31.y * a3);
        acc[4] += (f02.x * a0 + f12.x * a1w) + (f22.x * a2 + f32.x * a3);
        acc[5] += (f02.y * a0 + f12.y * a1w) + (f22.y * a2 + f32.y * a3);
        acc[6] += (f03.x * a0 + f13.x * a1w) + (f23.x * a2 + f33.x * a3);
        acc[7] += (f03.y * a0 + f13.y * a1w) + (f23.y * a2 + f33.y * a3);
    }
    for (; j < end; j++) {
        int2 p = g_epack[j];
        int src = p.x;
        float4 s = *reinterpret_cast<const float4*>(&g_s1[src * 4]);
        float4 e;
        e.x = __expf(lrelu(s.x + d.x)); e.y = __expf(lrelu(s.y + d.y));
        e.z = __expf(lrelu(s.z + d.z)); e.w = __expf(lrelu(s.w + d.w));
        den.x += e.x; den.y += e.y; den.z += e.z; den.w += e.w;
        float a = (h == 0) ? e.x : (h == 1) ? e.y : (h == 2) ? e.z : e.w;
        uint4 hv = *reinterpret_cast<const uint4*>(&g_h1h[(size_t)src * C1 + c0]);
        float2 f0 = __half22float2(*reinterpret_cast<__half2*>(&hv.x));
        float2 f1 = __half22float2(*reinterpret_cast<__half2*>(&hv.y));
        float2 f2 = __half22float2(*reinterpret_cast<__half2*>(&hv.z));
        float2 f3 = __half22float2(*reinterpret_cast<__half2*>(&hv.w));
        acc[0] += f0.x * a; acc[1] += f0.y * a;
        acc[2] += f1.x * a; acc[3] += f1.y * a;
        acc[4] += f2.x * a; acc[5] += f2.y * a;
        acc[6] += f3.x * a; acc[7] += f3.y * a;
    }

    float4 inv = make_float4(1.f / (den.x + EPS_SM), 1.f / (den.y + EPS_SM),
                             1.f / (den.z + EPS_SM), 1.f / (den.w + EPS_SM));

    // alpha writes, lane-parallel
    for (int jj = base + lane; jj < end; jj += 32) {
        int2 p = g_epack[jj];
        float4 s = *reinterpret_cast<const float4*>(&g_s1[p.x * 4]);
        float4 al;
        al.x = __expf(lrelu(s.x + d.x)) * inv.x;
        al.y = __expf(lrelu(s.y + d.y)) * inv.y;
        al.z = __expf(lrelu(s.z + d.z)) * inv.z;
        al.w = __expf(lrelu(s.w + d.w)) * inv.w;
        *reinterpret_cast<float4*>(&a1[(size_t)p.y * 4]) = al;
    }

    float invh = (h == 0) ? inv.x : (h == 1) ? inv.y : (h == 2) ? inv.z : inv.w;
#pragma unroll
    for (int i = 0; i < 8; i++) acc[i] *= invh;

    // epilogue: +b1, LayerNorm(256), ELU -> g_x2
    float4 ba = *reinterpret_cast<const float4*>(&b1[c0]);
    float4 bb = *reinterpret_cast<const float4*>(&b1[c0 + 4]);
    acc[0] += ba.x; acc[1] += ba.y; acc[2] += ba.z; acc[3] += ba.w;
    acc[4] += bb.x; acc[5] += bb.y; acc[6] += bb.z; acc[7] += bb.w;
    float sum = 0.f, sq = 0.f;
#pragma unroll
    for (int i = 0; i < 8; i++) { sum += acc[i]; sq += acc[i] * acc[i]; }
    sum = wredsum(sum); sq = wredsum(sq);
    float mu  = sum * (1.f / 256.f);
    float var = sq * (1.f / 256.f) - mu * mu;
    float rs  = rsqrtf(var + 1e-5f);
    float4 ga = *reinterpret_cast<const float4*>(&gam[c0]);
    float4 gb = *reinterpret_cast<const float4*>(&gam[c0 + 4]);
    float4 ea = *reinterpret_cast<const float4*>(&bet[c0]);
    float4 eb = *reinterpret_cast<const float4*>(&bet[c0 + 4]);
    float4 y0, y1;
    y0.x = eluf((acc[0] - mu) * rs * ga.x + ea.x);
    y0.y = eluf((acc[1] - mu) * rs * ga.y + ea.y);
    y0.z = eluf((acc[2] - mu) * rs * ga.z + ea.z);
    y0.w = eluf((acc[3] - mu) * rs * ga.w + ea.w);
    y1.x = eluf((acc[4] - mu) * rs * gb.x + eb.x);
    y1.y = eluf((acc[5] - mu) * rs * gb.y + eb.y);
    y1.z = eluf((acc[6] - mu) * rs * gb.z + eb.z);
    y1.w = eluf((acc[7] - mu) * rs * gb.w + eb.w);
    float4* orow = reinterpret_cast<float4*>(&g_x2[(size_t)n * C1 + c0]);
    orow[0] = y0; orow[1] = y1;
}

// ------------------------- layer 2: single-pass gather + LN + ELU + head -----
__global__ __launch_bounds__(256)
void agg2_kernel(float* __restrict__ a2, const float* __restrict__ b2,
                 const float* __restrict__ g2, const float* __restrict__ e2,
                 const float* __restrict__ hW1, const float* __restrict__ hb1,
                 const float* __restrict__ hW2, const float* __restrict__ hb2,
                 float* __restrict__ out) {
    __shared__ float w1s[64 * 32];
    __shared__ float w2s[32];
    __shared__ float b1s[32];
    __shared__ float zs[8][64];
    int tid = threadIdx.x;
    for (int i = tid; i < 64 * 32; i += 256) w1s[i] = hW1[i];
    if (tid < 32) { w2s[tid] = hW2[tid]; b1s[tid] = hb1[tid]; }
    __syncthreads();

    int w    = tid >> 5;
    int lane = tid & 31;
    int n = blockIdx.x * 8 + w;
    if (n >= N_NODES) return;

    int base = g_rowptr[n], end = g_rowptr[n + 1];
    float dd = g_d2[n];

    float a0 = 0.f, a1v = 0.f, den = 0.f;
    int c0 = lane * 2;
    int j = base;
    for (; j + 3 < end; j += 4) {
        int2 p0 = g_epack[j],     p1 = g_epack[j + 1];
        int2 p2 = g_epack[j + 2], p3 = g_epack[j + 3];
        float t0 = g_s2[p0.x], t1 = g_s2[p1.x];
        float t2 = g_s2[p2.x], t3 = g_s2[p3.x];
        unsigned u0 = *reinterpret_cast<const unsigned*>(&g_h2h[(size_t)p0.x * HID + c0]);
        unsigned u1 = *reinterpret_cast<const unsigned*>(&g_h2h[(size_t)p1.x * HID + c0]);
        unsigned u2 = *reinterpret_cast<const unsigned*>(&g_h2h[(size_t)p2.x * HID + c0]);
        unsigned u3 = *reinterpret_cast<const unsigned*>(&g_h2h[(size_t)p3.x * HID + c0]);
        float e0 = __expf(lrelu(t0 + dd));
        float e1 = __expf(lrelu(t1 + dd));
        float e2v = __expf(lrelu(t2 + dd));
        float e3 = __expf(lrelu(t3 + dd));
        float2 v0 = __half22float2(*reinterpret_cast<__half2*>(&u0));
        float2 v1 = __half22float2(*reinterpret_cast<__half2*>(&u1));
        float2 v2 = __half22float2(*reinterpret_cast<__half2*>(&u2));
        float2 v3 = __half22float2(*reinterpret_cast<__half2*>(&u3));
        den += (e0 + e1) + (e2v + e3);
        a0  += (v0.x * e0 + v1.x * e1) + (v2.x * e2v + v3.x * e3);
        a1v += (v0.y * e0 + v1.y * e1) + (v2.y * e2v + v3.y * e3);
    }
    for (; j < end; j++) {
        int2 p = g_epack[j];
        float e = __expf(lrelu(g_s2[p.x] + dd));
        unsigned u = *reinterpret_cast<const unsigned*>(&g_h2h[(size_t)p.x * HID + c0]);
        float2 v = __half22float2(*reinterpret_cast<__half2*>(&u));
        den += e; a0 += v.x * e; a1v += v.y * e;
    }
    float inv = 1.f / (den + EPS_SM);

    for (int jj = base + lane; jj < end; jj += 32) {
        int2 p = g_epack[jj];
        a2[p.y] = __expf(lrelu(g_s2[p.x] + dd)) * inv;
    }
    a0 *= inv; a1v *= inv;

    // +b2, LN(64), ELU
    a0  += b2[c0];
    a1v += b2[c0 + 1];
    float sum = wredsum(a0 + a1v);
    float sq  = wredsum(a0 * a0 + a1v * a1v);
    float mu  = sum * (1.f / 64.f);
    float var = sq * (1.f / 64.f) - mu * mu;
    float rs  = rsqrtf(var + 1e-5f);
    float y0 = eluf((a0  - mu) * rs * g2[c0]     + e2[c0]);
    float y1 = eluf((a1v - mu) * rs * g2[c0 + 1] + e2[c0 + 1]);
    zs[w][c0] = y0; zs[w][c0 + 1] = y1;
    __syncwarp();

    // MLP head: 64 -> 32 -> ReLU -> 1
    float acc = b1s[lane];
#pragma unroll
    for (int k = 0; k < 64; k++) acc += zs[w][k] * w1s[k * 32 + lane];
    acc = fmaxf(acc, 0.f);
    float p = wredsum(acc * w2s[lane]);
    if (lane == 0) out[n] = p + hb2[0];
}

// ------------------------- host launcher -------------------------------------
extern "C" void kernel_launch(void* const* d_in, const int* in_sizes, int n_in,
                              void* d_out, int out_size) {
    const float* x     = (const float*)d_in[0];
    const int*   ei    = (const int*)  d_in[1];
    const float* W1    = (const float*)d_in[2];
    const float* as1   = (const float*)d_in[3];
    const float* ad1   = (const float*)d_in[4];
    const float* b1    = (const float*)d_in[5];
    const float* W2    = (const float*)d_in[6];
    const float* as2   = (const float*)d_in[7];
    const float* ad2   = (const float*)d_in[8];
    const float* b2    = (const float*)d_in[9];
    const float* ln1g  = (const float*)d_in[10];
    const float* ln1b  = (const float*)d_in[11];
    const float* ln2g  = (const float*)d_in[12];
    const float* ln2b  = (const float*)d_in[13];
    const float* hW1   = (const float*)d_in[14];
    const float* hb1   = (const float*)d_in[15];
    const float* hW2   = (const float*)d_in[16];
    const float* hb2   = (const float*)d_in[17];
    float* out = (float*)d_out;

    // expected layout: out[N] | alpha1[ETOT*4] | alpha2[ETOT]
    size_t need = (size_t)N_NODES + (size_t)ETOT * (HEADS + 1);
    float *a1, *a2;
    if ((size_t)out_size >= need) {
        a1 = out + N_NODES;
        a2 = a1 + (size_t)ETOT * HEADS;
    } else {
        void* p;
        cudaGetSymbolAddress(&p, g_a1_fb); a1 = (float*)p;
        cudaGetSymbolAddress(&p, g_a2_fb); a2 = (float*)p;
    }

    auto cdiv = [](long a, long b) { return (int)((a + b - 1) / b); };

    float *px2, *ps1, *pd1, *ps2, *pd2;
    __half *ph1, *ph2;
    { void* p;
      cudaGetSymbolAddress(&p, g_h1h); ph1 = (__half*)p;
      cudaGetSymbolAddress(&p, g_x2);  px2 = (float*)p;
      cudaGetSymbolAddress(&p, g_h2h); ph2 = (__half*)p;
      cudaGetSymbolAddress(&p, g_s1);  ps1 = (float*)p;
      cudaGetSymbolAddress(&p, g_d1);  pd1 = (float*)p;
      cudaGetSymbolAddress(&p, g_s2);  ps2 = (float*)p;
      cudaGetSymbolAddress(&p, g_d2);  pd2 = (float*)p;
    }

    cudaFuncSetAttribute(gemm1_wmma_kernel,
                         cudaFuncAttributeMaxDynamicSharedMemorySize, G1_SMEM);
    cudaFuncSetAttribute(gemm2_wmma_kernel,
                         cudaFuncAttributeMaxDynamicSharedMemorySize, G2_SMEM);

    // side stream for the CSR build (fork-join; both branches rejoin before agg1)
    cudaStream_t side;
    cudaStreamCreateWithFlags(&side, cudaStreamNonBlocking);
    cudaEvent_t evF, evJ;
    cudaEventCreateWithFlags(&evF, cudaEventDisableTiming);
    cudaEventCreateWithFlags(&evJ, cudaEventDisableTiming);

    cudaEventRecord(evF, 0);
    cudaStreamWaitEvent(side, evF, 0);

    // ---- CSR build on side stream (independent of GEMM1) ----
    zero_cnt_kernel<<<cdiv(N_PAD / 4, 256), 256, 0, side>>>();
    hist_kernel<<<cdiv(cdiv(ETOT, 8), 256), 256, 0, side>>>(ei);
    scan_kernel<<<1, SCAN_T, 0, side>>>();
    scatter_kernel<<<cdiv(cdiv(ETOT, 8), 256), 256, 0, side>>>(ei);
    cudaEventRecord(evJ, side);

    // ---- layer 1: W1/W2->fp16, then HMMA GEMM + fused logits (main stream) ----
    conv_w_kernel<<<cdiv((F_IN * C1 + C1 * HID) / 4, 256), 256>>>(W1, W2);
    gemm1_wmma_kernel<<<cdiv(N_NODES, G1_BM), 256, G1_SMEM>>>(
        x, as1, ad1, ph1, ps1, pd1, N_NODES);

    cudaStreamWaitEvent(0, evJ, 0);     // join: agg1 needs CSR + h1 + s1/d1
    agg1_kernel<<<cdiv((long)N_NODES * 32, 256), 256>>>(a1, b1, ln1g, ln1b);

    // ---- layer 2: HMMA GEMM + fused logits ----
    gemm2_wmma_kernel<<<cdiv(N_NODES, G2_BM), 128, G2_SMEM>>>(
        px2, as2, ad2, ph2, ps2, pd2, N_NODES);
    agg2_kernel<<<cdiv(N_NODES, 8), 256>>>(a2, b2, ln2g, ln2b, hW1, hb1, hW2, hb2, out);
}

// round 12
// speedup vs baseline: 1.0621x; 1.0621x over previous
#include <cuda_runtime.h>
#include <cuda_fp16.h>
#include <mma.h>
#include <math.h>

using namespace nvcuda;

#define N_NODES 50000
#define E_EDGES 800000
#define ETOT    (E_EDGES + N_NODES)   // 850000
#define F_IN    128
#define HID     64
#define HEADS   4
#define C1      (HEADS * HID)         // 256
#define SLOPE   0.2f
#define EPS_SM  1e-16f

#define SCAN_T  1024
#define SCAN_CH 52                     // 52*1024 = 53248 >= N_NODES, /4
#define N_PAD   (SCAN_T * SCAN_CH)

// wmma gemm1 tiling
#define G1_BM    64
#define G1_ALD   136
#define G1_WLD   264
#define G1_SLD   264
#define G1_SMEM  ((G1_BM * G1_ALD + 128 * G1_WLD) * 2 > G1_BM * G1_SLD * 4 ? \
                  (G1_BM * G1_ALD + 128 * G1_WLD) * 2 : G1_BM * G1_SLD * 4)

// wmma gemm2 tiling (64 rows x 64 cols x K=256, 4 warps)
#define G2_BM    64
#define G2_ALD   264
#define G2_WLD   72
#define G2_SLD   72
#define G2_SMEM  ((G2_BM * G2_ALD + 256 * G2_WLD) * 2)

// ------------------------- device scratch (no allocs allowed) ---------------
__device__ __half g_h1h[(size_t)N_NODES * C1];    // x @ W1 (fp16 storage)
__device__ float  g_x2 [(size_t)N_NODES * C1];    // layer1 output after LN/ELU
__device__ __half g_h2h[(size_t)N_NODES * HID];   // x2 @ W2 (fp16 storage)
__device__ __half g_w1h[F_IN * C1];
__device__ __half g_w2h[C1 * HID];
__device__ float g_s1  [N_NODES * HEADS];
__device__ float g_d1  [N_NODES * HEADS];
__device__ float g_s2  [N_NODES];
__device__ float g_d2  [N_NODES];
// CSR by destination (rebuilt every launch; deterministic work)
__device__ __align__(16) int g_cnt   [N_PAD];
__device__ __align__(16) int g_rowptr[N_PAD + 4];
__device__ __align__(16) int g_wofs  [N_PAD + 4];
__device__ int2 g_epack[ETOT];                    // {src, eid} per CSR slot
// fallback alpha scratch in case d_out layout differs from expectation
__device__ float g_a1_fb[(size_t)ETOT * HEADS];
__device__ float g_a2_fb[(size_t)ETOT];

// ------------------------- helpers ------------------------------------------
__device__ __forceinline__ float lrelu(float v) { return v > 0.f ? v : SLOPE * v; }
__device__ __forceinline__ float eluf(float v)  { return v > 0.f ? v : expm1f(v); }

__device__ __forceinline__ float wredsum(float v) {
#pragma unroll
    for (int o = 16; o > 0; o >>= 1) v += __shfl_xor_sync(0xffffffffu, v, o);
    return v;
}

__device__ __forceinline__ uint2 pack_half4(float4 v) {
    __half2 h0 = __floats2half2_rn(v.x, v.y);
    __half2 h1 = __floats2half2_rn(v.z, v.w);
    return make_uint2(*reinterpret_cast<unsigned*>(&h0),
                      *reinterpret_cast<unsigned*>(&h1));
}

// ------------------------- CSR build -----------------------------------------
__global__ void zero_cnt_kernel() {
    int i = blockIdx.x * blockDim.x + threadIdx.x;
    if (i < N_PAD / 4) *reinterpret_cast<int4*>(&g_cnt[i * 4]) = make_int4(0, 0, 0, 0);
}

__global__ void hist_kernel(const int* __restrict__ ei) {
    int i0 = (blockIdx.x * blockDim.x + threadIdx.x) * 8;
    if (i0 >= ETOT) return;
    if (i0 + 8 <= E_EDGES) {
        int4 d0 = *reinterpret_cast<const int4*>(&ei[E_EDGES + i0]);
        int4 d1 = *reinterpret_cast<const int4*>(&ei[E_EDGES + i0 + 4]);
        atomicAdd(&g_cnt[d0.x], 1); atomicAdd(&g_cnt[d0.y], 1);
        atomicAdd(&g_cnt[d0.z], 1); atomicAdd(&g_cnt[d0.w], 1);
        atomicAdd(&g_cnt[d1.x], 1); atomicAdd(&g_cnt[d1.y], 1);
        atomicAdd(&g_cnt[d1.z], 1); atomicAdd(&g_cnt[d1.w], 1);
    } else {
#pragma unroll
        for (int t = 0; t < 8; t++) {
            int e = i0 + t;
            if (e < ETOT) {
                int dst = (e < E_EDGES) ? ei[E_EDGES + e] : e - E_EDGES;
                atomicAdd(&g_cnt[dst], 1);
            }
        }
    }
}

__global__ __launch_bounds__(SCAN_T) void scan_kernel() {
    __shared__ int sums[SCAN_T];
    int t = threadIdx.x;
    int lo = t * SCAN_CH;
    const int4* cp = reinterpret_cast<const int4*>(&g_cnt[lo]);
    int local = 0;
#pragma unroll
    for (int i = 0; i < SCAN_CH / 4; i++) {
        int4 c = cp[i];
        local += c.x + c.y + c.z + c.w;
    }
    sums[t] = local;
    __syncthreads();
    for (int off = 1; off < SCAN_T; off <<= 1) {
        int v = (t >= off) ? sums[t - off] : 0;
        __syncthreads();
        sums[t] += v;
        __syncthreads();
    }
    int run = sums[t] - local;
    int4* rp = reinterpret_cast<int4*>(&g_rowptr[lo]);
    int4* wp = reinterpret_cast<int4*>(&g_wofs[lo]);
#pragma unroll
    for (int i = 0; i < SCAN_CH / 4; i++) {
        int4 c = cp[i];
        int4 o;
        o.x = run; run += c.x;
        o.y = run; run += c.y;
        o.z = run; run += c.z;
        o.w = run; run += c.w;
        rp[i] = o; wp[i] = o;
    }
}

__global__ void scatter_kernel(const int* __restrict__ ei) {
    int i0 = (blockIdx.x * blockDim.x + threadIdx.x) * 8;
    if (i0 >= ETOT) return;
    if (i0 + 8 <= E_EDGES) {
        int4 s0 = *reinterpret_cast<const int4*>(&ei[i0]);
        int4 s1 = *reinterpret_cast<const int4*>(&ei[i0 + 4]);
        int4 d0 = *reinterpret_cast<const int4*>(&ei[E_EDGES + i0]);
        int4 d1 = *reinterpret_cast<const int4*>(&ei[E_EDGES + i0 + 4]);
        int sl;
        sl = atomicAdd(&g_wofs[d0.x], 1); g_epack[sl] = make_int2(s0.x, i0);
        sl = atomicAdd(&g_wofs[d0.y], 1); g_epack[sl] = make_int2(s0.y, i0 + 1);
        sl = atomicAdd(&g_wofs[d0.z], 1); g_epack[sl] = make_int2(s0.z, i0 + 2);
        sl = atomicAdd(&g_wofs[d0.w], 1); g_epack[sl] = make_int2(s0.w, i0 + 3);
        sl = atomicAdd(&g_wofs[d1.x], 1); g_epack[sl] = make_int2(s1.x, i0 + 4);
        sl = atomicAdd(&g_wofs[d1.y], 1); g_epack[sl] = make_int2(s1.y, i0 + 5);
        sl = atomicAdd(&g_wofs[d1.z], 1); g_epack[sl] = make_int2(s1.z, i0 + 6);
        sl = atomicAdd(&g_wofs[d1.w], 1); g_epack[sl] = make_int2(s1.w, i0 + 7);
    } else {
#pragma unroll
        for (int t = 0; t < 8; t++) {
            int e = i0 + t;
            if (e < ETOT) {
                int src, dst;
                if (e < E_EDGES) { src = ei[e]; dst = ei[E_EDGES + e]; }
                else             { src = dst = e - E_EDGES; }
                int slot = atomicAdd(&g_wofs[dst], 1);
                g_epack[slot] = make_int2(src, e);
            }
        }
    }
}

// ------------------------- W1+W2 fp32 -> fp16 (once per launch) --------------
__global__ void conv_w_kernel(const float* __restrict__ W1,
                              const float* __restrict__ W2) {
    int i4 = (blockIdx.x * blockDim.x + threadIdx.x) * 4;
    if (i4 < F_IN * C1) {
        float4 v = *reinterpret_cast<const float4*>(&W1[i4]);
        *reinterpret_cast<uint2*>(&g_w1h[i4]) = pack_half4(v);
    } else if (i4 < F_IN * C1 + C1 * HID) {
        int j4 = i4 - F_IN * C1;
        float4 v = *reinterpret_cast<const float4*>(&W2[j4]);
        *reinterpret_cast<uint2*>(&g_w2h[j4]) = pack_half4(v);
    }
}

// ---- layer-1 GEMM on tensor cores (HMMA) + fused logits ---------------------
__global__ __launch_bounds__(256)
void gemm1_wmma_kernel(const float* __restrict__ X,
                       const float* __restrict__ asrc, const float* __restrict__ adst,
                       __half* __restrict__ Yh,
                       float* __restrict__ S, float* __restrict__ D, int nrows) {
    extern __shared__ char smraw[];
    __half* Ah  = reinterpret_cast<__half*>(smraw);
    __half* Wh  = reinterpret_cast<__half*>(smraw) + G1_BM * G1_ALD;
    float*  stg = reinterpret_cast<float*>(smraw);

    int tid = threadIdx.x;
    int rowbase = blockIdx.x * G1_BM;

    for (int i = tid * 4; i < G1_BM * F_IN; i += 256 * 4) {
        int r = i >> 7, c = i & 127;
        int gr = rowbase + r;
        float4 v = (gr < nrows) ? *reinterpret_cast<const float4*>(&X[(size_t)gr * F_IN + c])
                                : make_float4(0.f, 0.f, 0.f, 0.f);
        *reinterpret_cast<uint2*>(&Ah[r * G1_ALD + c]) = pack_half4(v);
    }
    for (int i = tid * 8; i < F_IN * C1; i += 256 * 8) {
        int k = i >> 8, c = i & 255;
        uint4 v = *reinterpret_cast<const uint4*>(&g_w1h[i]);
        *reinterpret_cast<uint4*>(&Wh[k * G1_WLD + c]) = v;
    }
    __syncthreads();

    int w = tid >> 5;
    int r0 = (w & 3) * 16;
    int cb = (w >> 2) * 128;

    wmma::fragment<wmma::accumulator, 16, 16, 16, float> acc[8];
#pragma unroll
    for (int f = 0; f < 8; f++) wmma::fill_fragment(acc[f], 0.f);

#pragma unroll
    for (int kk = 0; kk < F_IN; kk += 16) {
        wmma::fragment<wmma::matrix_a, 16, 16, 16, __half, wmma::row_major> af;
        wmma::load_matrix_sync(af, Ah + r0 * G1_ALD + kk, G1_ALD);
#pragma unroll
        for (int f = 0; f < 8; f++) {
            wmma::fragment<wmma::matrix_b, 16, 16, 16, __half, wmma::row_major> bf;
            wmma::load_matrix_sync(bf, Wh + kk * G1_WLD + cb + f * 16, G1_WLD);
            wmma::mma_sync(acc[f], af, bf, acc[f]);
        }
    }
    __syncthreads();
#pragma unroll
    for (int f = 0; f < 8; f++)
        wmma::store_matrix_sync(stg + r0 * G1_SLD + cb + f * 16, acc[f],
                                G1_SLD, wmma::mem_row_major);
    __syncthreads();

    int r = tid >> 2, q = tid & 3;
    int gr = rowbase + r;
    if (gr < nrows) {
        const float* as = asrc + q * 64;
        const float* ad = adst + q * 64;
        const float* row = stg + r * G1_SLD + q * 64;
        __half* yp = Yh + (size_t)gr * C1 + q * 64;
        float s = 0.f, dd = 0.f;
#pragma unroll
        for (int i = 0; i < 64; i += 4) {
            float4 v = *reinterpret_cast<const float4*>(&row[i]);
            float4 a = *reinterpret_cast<const float4*>(&as[i]);
            float4 b = *reinterpret_cast<const float4*>(&ad[i]);
            s  += v.x * a.x + v.y * a.y + v.z * a.z + v.w * a.w;
            dd += v.x * b.x + v.y * b.y + v.z * b.z + v.w * b.w;
            *reinterpret_cast<uint2*>(&yp[i]) = pack_half4(v);
        }
        S[gr * 4 + q] = s;
        D[gr * 4 + q] = dd;
    }
}

// ---- layer-2 GEMM on tensor cores (HMMA) + fused logits ---------------------
__global__ __launch_bounds__(128)
void gemm2_wmma_kernel(const float* __restrict__ X,
                       const float* __restrict__ asrc, const float* __restrict__ adst,
                       __half* __restrict__ Yh,
                       float* __restrict__ S, float* __restrict__ D, int nrows) {
    extern __shared__ char smraw[];
    __half* Ah  = reinterpret_cast<__half*>(smraw);
    __half* Wh  = reinterpret_cast<__half*>(smraw) + G2_BM * G2_ALD;
    float*  stg = reinterpret_cast<float*>(smraw);

    int tid = threadIdx.x;
    int rowbase = blockIdx.x * G2_BM;

    for (int i = tid * 4; i < G2_BM * C1; i += 128 * 4) {
        int r = i >> 8, c = i & 255;
        int gr = rowbase + r;
        float4 v = (gr < nrows) ? *reinterpret_cast<const float4*>(&X[(size_t)gr * C1 + c])
                                : make_float4(0.f, 0.f, 0.f, 0.f);
        *reinterpret_cast<uint2*>(&Ah[r * G2_ALD + c]) = pack_half4(v);
    }
    for (int i = tid * 8; i < C1 * HID; i += 128 * 8) {
        int k = i >> 6, c = i & 63;
        uint4 v = *reinterpret_cast<const uint4*>(&g_w2h[i]);
        *reinterpret_cast<uint4*>(&Wh[k * G2_WLD + c]) = v;
    }
    __syncthreads();

    int w = tid >> 5;
    int r0 = w * 16;

    wmma::fragment<wmma::accumulator, 16, 16, 16, float> acc[4];
#pragma unroll
    for (int f = 0; f < 4; f++) wmma::fill_fragment(acc[f], 0.f);

#pragma unroll
    for (int kk = 0; kk < C1; kk += 16) {
        wmma::fragment<wmma::matrix_a, 16, 16, 16, __half, wmma::row_major> af;
        wmma::load_matrix_sync(af, Ah + r0 * G2_ALD + kk, G2_ALD);
#pragma unroll
        for (int f = 0; f < 4; f++) {
            wmma::fragment<wmma::matrix_b, 16, 16, 16, __half, wmma::row_major> bf;
            wmma::load_matrix_sync(bf, Wh + kk * G2_WLD + f * 16, G2_WLD);
            wmma::mma_sync(acc[f], af, bf, acc[f]);
        }
    }
    __syncthreads();
#pragma unroll
    for (int f = 0; f < 4; f++)
        wmma::store_matrix_sync(stg + r0 * G2_SLD + f * 16, acc[f],
                                G2_SLD, wmma::mem_row_major);
    __syncthreads();

    int r = tid >> 1, half = tid & 1;
    int c0 = half * 32;
    int gr = rowbase + r;
    float s = 0.f, dd = 0.f;
    if (gr < nrows) {
        const float* row = stg + r * G2_SLD + c0;
        __half* yp = Yh + (size_t)gr * HID + c0;
#pragma unroll
        for (int i = 0; i < 32; i += 4) {
            float4 v = *reinterpret_cast<const float4*>(&row[i]);
            float4 a = *reinterpret_cast<const float4*>(&asrc[c0 + i]);
            float4 b = *reinterpret_cast<const float4*>(&adst[c0 + i]);
            s  += v.x * a.x + v.y * a.y + v.z * a.z + v.w * a.w;
            dd += v.x * b.x + v.y * b.y + v.z * b.z + v.w * b.w;
            *reinterpret_cast<uint2*>(&yp[i]) = pack_half4(v);
        }
    }
    s  += __shfl_xor_sync(0xffffffffu, s, 1);
    dd += __shfl_xor_sync(0xffffffffu, dd, 1);
    if (gr < nrows && half == 0) { S[gr] = s; D[gr] = dd; }
}

// ------------------------- layer 1: single-pass gather + LN + ELU ------------
// 2-edge unroll (R10 proven version; 4-edge regressed via register pressure)
__global__ __launch_bounds__(256)
void agg1_kernel(float* __restrict__ a1, const float* __restrict__ b1,
                 const float* __restrict__ gam, const float* __restrict__ bet) {
    int n    = (blockIdx.x * blockDim.x + threadIdx.x) >> 5;
    int lane = threadIdx.x & 31;
    if (n >= N_NODES) return;
    int base = g_rowptr[n], end = g_rowptr[n + 1];
    float4 d = *reinterpret_cast<const float4*>(&g_d1[n * 4]);

    int h  = lane >> 3;
    int c0 = lane * 8;
    float acc[8];
#pragma unroll
    for (int i = 0; i < 8; i++) acc[i] = 0.f;
    float4 den = make_float4(0.f, 0.f, 0.f, 0.f);

    int j = base;
    for (; j + 1 < end; j += 2) {
        int2 p0 = g_epack[j], p1 = g_epack[j + 1];
        int src0 = p0.x, src1 = p1.x;
        float4 s0 = *reinterpret_cast<const float4*>(&g_s1[src0 * 4]);
        float4 s1 = *reinterpret_cast<const float4*>(&g_s1[src1 * 4]);
        uint4 hv0 = *reinterpret_cast<const uint4*>(&g_h1h[(size_t)src0 * C1 + c0]);
        uint4 hv1 = *reinterpret_cast<const uint4*>(&g_h1h[(size_t)src1 * C1 + c0]);
        float4 e0, e1;
        e0.x = __expf(lrelu(s0.x + d.x)); e0.y = __expf(lrelu(s0.y + d.y));
        e0.z = __expf(lrelu(s0.z + d.z)); e0.w = __expf(lrelu(s0.w + d.w));
        e1.x = __expf(lrelu(s1.x + d.x)); e1.y = __expf(lrelu(s1.y + d.y));
        e1.z = __expf(lrelu(s1.z + d.z)); e1.w = __expf(lrelu(s1.w + d.w));
        den.x += e0.x + e1.x; den.y += e0.y + e1.y;
        den.z += e0.z + e1.z; den.w += e0.w + e1.w;
        float a0 = (h == 0) ? e0.x : (h == 1) ? e0.y : (h == 2) ? e0.z : e0.w;
        float a1w = (h == 0) ? e1.x : (h == 1) ? e1.y : (h == 2) ? e1.z : e1.w;
        float2 f00 = __half22float2(*reinterpret_cast<__half2*>(&hv0.x));
        float2 f01 = __half22float2(*reinterpret_cast<__half2*>(&hv0.y));
        float2 f02 = __half22float2(*reinterpret_cast<__half2*>(&hv0.z));
        float2 f03 = __half22float2(*reinterpret_cast<__half2*>(&hv0.w));
        float2 f10 = __half22float2(*reinterpret_cast<__half2*>(&hv1.x));
        float2 f11 = __half22float2(*reinterpret_cast<__half2*>(&hv1.y));
        float2 f12 = __half22float2(*reinterpret_cast<__half2*>(&hv1.z));
        float2 f13 = __half22float2(*reinterpret_cast<__half2*>(&hv1.w));
        acc[0] += f00.x * a0 + f10.x * a1w; acc[1] += f00.y * a0 + f10.y * a1w;
        acc[2] += f01.x * a0 + f11.x * a1w; acc[3] += f01.y * a0 + f11.y * a1w;
        acc[4] += f02.x * a0 + f12.x * a1w; acc[5] += f02.y * a0 + f12.y * a1w;
        acc[6] += f03.x * a0 + f13.x * a1w; acc[7] += f03.y * a0 + f13.y * a1w;
    }
    if (j < end) {
        int2 p = g_epack[j];
        int src = p.x;
        float4 s = *reinterpret_cast<const float4*>(&g_s1[src * 4]);
        float4 e;
        e.x = __expf(lrelu(s.x + d.x)); e.y = __expf(lrelu(s.y + d.y));
        e.z = __expf(lrelu(s.z + d.z)); e.w = __expf(lrelu(s.w + d.w));
        den.x += e.x; den.y += e.y; den.z += e.z; den.w += e.w;
        float a = (h == 0) ? e.x : (h == 1) ? e.y : (h == 2) ? e.z : e.w;
        uint4 hv = *reinterpret_cast<const uint4*>(&g_h1h[(size_t)src * C1 + c0]);
        float2 f0 = __half22float2(*reinterpret_cast<__half2*>(&hv.x));
        float2 f1 = __half22float2(*reinterpret_cast<__half2*>(&hv.y));
        float2 f2 = __half22float2(*reinterpret_cast<__half2*>(&hv.z));
        float2 f3 = __half22float2(*reinterpret_cast<__half2*>(&hv.w));
        acc[0] += f0.x * a; acc[1] += f0.y * a;
        acc[2] += f1.x * a; acc[3] += f1.y * a;
        acc[4] += f2.x * a; acc[5] += f2.y * a;
        acc[6] += f3.x * a; acc[7] += f3.y * a;
    }

    float4 inv = make_float4(1.f / (den.x + EPS_SM), 1.f / (den.y + EPS_SM),
                             1.f / (den.z + EPS_SM), 1.f / (den.w + EPS_SM));

    // alpha writes, lane-parallel
    for (int jj = base + lane; jj < end; jj += 32) {
        int2 p = g_epack[jj];
        float4 s = *reinterpret_cast<const float4*>(&g_s1[p.x * 4]);
        float4 al;
        al.x = __expf(lrelu(s.x + d.x)) * inv.x;
        al.y = __expf(lrelu(s.y + d.y)) * inv.y;
        al.z = __expf(lrelu(s.z + d.z)) * inv.z;
        al.w = __expf(lrelu(s.w + d.w)) * inv.w;
        *reinterpret_cast<float4*>(&a1[(size_t)p.y * 4]) = al;
    }

    float invh = (h == 0) ? inv.x : (h == 1) ? inv.y : (h == 2) ? inv.z : inv.w;
#pragma unroll
    for (int i = 0; i < 8; i++) acc[i] *= invh;

    // epilogue: +b1, LayerNorm(256), ELU -> g_x2
    float4 ba = *reinterpret_cast<const float4*>(&b1[c0]);
    float4 bb = *reinterpret_cast<const float4*>(&b1[c0 + 4]);
    acc[0] += ba.x; acc[1] += ba.y; acc[2] += ba.z; acc[3] += ba.w;
    acc[4] += bb.x; acc[5] += bb.y; acc[6] += bb.z; acc[7] += bb.w;
    float sum = 0.f, sq = 0.f;
#pragma unroll
    for (int i = 0; i < 8; i++) { sum += acc[i]; sq += acc[i] * acc[i]; }
    sum = wredsum(sum); sq = wredsum(sq);
    float mu  = sum * (1.f / 256.f);
    float var = sq * (1.f / 256.f) - mu * mu;
    float rs  = rsqrtf(var + 1e-5f);
    float4 ga = *reinterpret_cast<const float4*>(&gam[c0]);
    float4 gb = *reinterpret_cast<const float4*>(&gam[c0 + 4]);
    float4 ea = *reinterpret_cast<const float4*>(&bet[c0]);
    float4 eb = *reinterpret_cast<const float4*>(&bet[c0 + 4]);
    float4 y0, y1;
    y0.x = eluf((acc[0] - mu) * rs * ga.x + ea.x);
    y0.y = eluf((acc[1] - mu) * rs * ga.y + ea.y);
    y0.z = eluf((acc[2] - mu) * rs * ga.z + ea.z);
    y0.w = eluf((acc[3] - mu) * rs * ga.w + ea.w);
    y1.x = eluf((acc[4] - mu) * rs * gb.x + eb.x);
    y1.y = eluf((acc[5] - mu) * rs * gb.y + eb.y);
    y1.z = eluf((acc[6] - mu) * rs * gb.z + eb.z);
    y1.w = eluf((acc[7] - mu) * rs * gb.w + eb.w);
    float4* orow = reinterpret_cast<float4*>(&g_x2[(size_t)n * C1 + c0]);
    orow[0] = y0; orow[1] = y1;
}

// ------------------------- layer 2: single-pass gather + LN + ELU + head -----
// 4-edge unroll (cheap registers here: 4 scalars + 4 float2)
__global__ __launch_bounds__(256)
void agg2_kernel(float* __restrict__ a2, const float* __restrict__ b2,
                 const float* __restrict__ g2, const float* __restrict__ e2,
                 const float* __restrict__ hW1, const float* __restrict__ hb1,
                 const float* __restrict__ hW2, const float* __restrict__ hb2,
                 float* __restrict__ out) {
    __shared__ float w1s[64 * 32];
    __shared__ float w2s[32];
    __shared__ float b1s[32];
    __shared__ float zs[8][64];
    int tid = threadIdx.x;
    for (int i = tid; i < 64 * 32; i += 256) w1s[i] = hW1[i];
    if (tid < 32) { w2s[tid] = hW2[tid]; b1s[tid] = hb1[tid]; }
    __syncthreads();

    int w    = tid >> 5;
    int lane = tid & 31;
    int n = blockIdx.x * 8 + w;
    if (n >= N_NODES) return;

    int base = g_rowptr[n], end = g_rowptr[n + 1];
    float dd = g_d2[n];

    float a0 = 0.f, a1v = 0.f, den = 0.f;
    int c0 = lane * 2;
    int j = base;
    for (; j + 3 < end; j += 4) {
        int2 p0 = g_epack[j],     p1 = g_epack[j + 1];
        int2 p2 = g_epack[j + 2], p3 = g_epack[j + 3];
        float t0 = g_s2[p0.x], t1 = g_s2[p1.x];
        float t2 = g_s2[p2.x], t3 = g_s2[p3.x];
        unsigned u0 = *reinterpret_cast<const unsigned*>(&g_h2h[(size_t)p0.x * HID + c0]);
        unsigned u1 = *reinterpret_cast<const unsigned*>(&g_h2h[(size_t)p1.x * HID + c0]);
        unsigned u2 = *reinterpret_cast<const unsigned*>(&g_h2h[(size_t)p2.x * HID + c0]);
        unsigned u3 = *reinterpret_cast<const unsigned*>(&g_h2h[(size_t)p3.x * HID + c0]);
        float e0 = __expf(lrelu(t0 + dd));
        float e1 = __expf(lrelu(t1 + dd));
        float e2v = __expf(lrelu(t2 + dd));
        float e3 = __expf(lrelu(t3 + dd));
        float2 v0 = __half22float2(*reinterpret_cast<__half2*>(&u0));
        float2 v1 = __half22float2(*reinterpret_cast<__half2*>(&u1));
        float2 v2 = __half22float2(*reinterpret_cast<__half2*>(&u2));
        float2 v3 = __half22float2(*reinterpret_cast<__half2*>(&u3));
        den += (e0 + e1) + (e2v + e3);
        a0  += (v0.x * e0 + v1.x * e1) + (v2.x * e2v + v3.x * e3);
        a1v += (v0.y * e0 + v1.y * e1) + (v2.y * e2v + v3.y * e3);
    }
    for (; j < end; j++) {
        int2 p = g_epack[j];
        float e = __expf(lrelu(g_s2[p.x] + dd));
        unsigned u = *reinterpret_cast<const unsigned*>(&g_h2h[(size_t)p.x * HID + c0]);
        float2 v = __half22float2(*reinterpret_cast<__half2*>(&u));
        den += e; a0 += v.x * e; a1v += v.y * e;
    }
    float inv = 1.f / (den + EPS_SM);

    for (int jj = base + lane; jj < end; jj += 32) {
        int2 p = g_epack[jj];
        a2[p.y] = __expf(lrelu(g_s2[p.x] + dd)) * inv;
    }
    a0 *= inv; a1v *= inv;

    // +b2, LN(64), ELU
    a0  += b2[c0];
    a1v += b2[c0 + 1];
    float sum = wredsum(a0 + a1v);
    float sq  = wredsum(a0 * a0 + a1v * a1v);
    float mu  = sum * (1.f / 64.f);
    float var = sq * (1.f / 64.f) - mu * mu;
    float rs  = rsqrtf(var + 1e-5f);
    float y0 = eluf((a0  - mu) * rs * g2[c0]     + e2[c0]);
    float y1 = eluf((a1v - mu) * rs * g2[c0 + 1] + e2[c0 + 1]);
    zs[w][c0] = y0; zs[w][c0 + 1] = y1;
    __syncwarp();

    // MLP head: 64 -> 32 -> ReLU -> 1
    float acc = b1s[lane];
#pragma unroll
    for (int k = 0; k < 64; k++) acc += zs[w][k] * w1s[k * 32 + lane];
    acc = fmaxf(acc, 0.f);
    float p = wredsum(acc * w2s[lane]);
    if (lane == 0) out[n] = p + hb2[0];
}

// ------------------------- host launcher -------------------------------------
extern "C" void kernel_launch(void* const* d_in, const int* in_sizes, int n_in,
                              void* d_out, int out_size) {
    const float* x     = (const float*)d_in[0];
    const int*   ei    = (const int*)  d_in[1];
    const float* W1    = (const float*)d_in[2];
    const float* as1   = (const float*)d_in[3];
    const float* ad1   = (const float*)d_in[4];
    const float* b1    = (const float*)d_in[5];
    const float* W2    = (const float*)d_in[6];
    const float* as2   = (const float*)d_in[7];
    const float* ad2   = (const float*)d_in[8];
    const float* b2    = (const float*)d_in[9];
    const float* ln1g  = (const float*)d_in[10];
    const float* ln1b  = (const float*)d_in[11];
    const float* ln2g  = (const float*)d_in[12];
    const float* ln2b  = (const float*)d_in[13];
    const float* hW1   = (const float*)d_in[14];
    const float* hb1   = (const float*)d_in[15];
    const float* hW2   = (const float*)d_in[16];
    const float* hb2   = (const float*)d_in[17];
    float* out = (float*)d_out;

    // expected layout: out[N] | alpha1[ETOT*4] | alpha2[ETOT]
    size_t need = (size_t)N_NODES + (size_t)ETOT * (HEADS + 1);
    float *a1, *a2;
    if ((size_t)out_size >= need) {
        a1 = out + N_NODES;
        a2 = a1 + (size_t)ETOT * HEADS;
    } else {
        void* p;
        cudaGetSymbolAddress(&p, g_a1_fb); a1 = (float*)p;
        cudaGetSymbolAddress(&p, g_a2_fb); a2 = (float*)p;
    }

    auto cdiv = [](long a, long b) { return (int)((a + b - 1) / b); };

    float *px2, *ps1, *pd1, *ps2, *pd2;
    __half *ph1, *ph2;
    { void* p;
      cudaGetSymbolAddress(&p, g_h1h); ph1 = (__half*)p;
      cudaGetSymbolAddress(&p, g_x2);  px2 = (float*)p;
      cudaGetSymbolAddress(&p, g_h2h); ph2 = (__half*)p;
      cudaGetSymbolAddress(&p, g_s1);  ps1 = (float*)p;
      cudaGetSymbolAddress(&p, g_d1);  pd1 = (float*)p;
      cudaGetSymbolAddress(&p, g_s2);  ps2 = (float*)p;
      cudaGetSymbolAddress(&p, g_d2);  pd2 = (float*)p;
    }

    cudaFuncSetAttribute(gemm1_wmma_kernel,
                         cudaFuncAttributeMaxDynamicSharedMemorySize, G1_SMEM);
    cudaFuncSetAttribute(gemm2_wmma_kernel,
                         cudaFuncAttributeMaxDynamicSharedMemorySize, G2_SMEM);

    // side stream for the CSR build (fork-join; both branches rejoin before agg1)
    cudaStream_t side;
    cudaStreamCreateWithFlags(&side, cudaStreamNonBlocking);
    cudaEvent_t evF, evJ;
    cudaEventCreateWithFlags(&evF, cudaEventDisableTiming);
    cudaEventCreateWithFlags(&evJ, cudaEventDisableTiming);

    cudaEventRecord(evF, 0);
    cudaStreamWaitEvent(side, evF, 0);

    // ---- CSR build on side stream (independent of GEMM1) ----
    zero_cnt_kernel<<<cdiv(N_PAD / 4, 256), 256, 0, side>>>();
    hist_kernel<<<cdiv(cdiv(ETOT, 8), 256), 256, 0, side>>>(ei);
    scan_kernel<<<1, SCAN_T, 0, side>>>();
    scatter_kernel<<<cdiv(cdiv(ETOT, 8), 256), 256, 0, side>>>(ei);
    cudaEventRecord(evJ, side);

    // ---- layer 1: W1/W2->fp16, then HMMA GEMM + fused logits (main stream) ----
    conv_w_kernel<<<cdiv((F_IN * C1 + C1 * HID) / 4, 256), 256>>>(W1, W2);
    gemm1_wmma_kernel<<<cdiv(N_NODES, G1_BM), 256, G1_SMEM>>>(
        x, as1, ad1, ph1, ps1, pd1, N_NODES);

    cudaStreamWaitEvent(0, evJ, 0);     // join: agg1 needs CSR + h1 + s1/d1
    agg1_kernel<<<cdiv((long)N_NODES * 32, 256), 256>>>(a1, b1, ln1g, ln1b);

    // ---- layer 2: HMMA GEMM + fused logits ----
    gemm2_wmma_kernel<<<cdiv(N_NODES, G2_BM), 128, G2_SMEM>>>(
        px2, as2, ad2, ph2, ps2, pd2, N_NODES);
    agg2_kernel<<<cdiv(N_NODES, 8), 256>>>(a2, b2, ln2g, ln2b, hW1, hb1, hW2, hb2, out);
}